// round 12
// baseline (speedup 1.0000x reference)
#include <cuda_runtime.h>
#include <cuda_fp16.h>
#include <cstdint>

// ---------------------------------------------------------------------------
// SparseConv2D == dense VALID 3x3 conv (R3 derivation) * per-14x14-block
// active flag.  mma.sync m16n8k16 FP16 implicit GEMM (f32 accumulate).
// R10: warp-specialized pipeline.  Warps 0-7 compute a 16-row x 32-col chunk
// while warps 8-9 stage the next chunk's 16 input rows into a 34-row ring
// buffer (18 in-use + 16 incoming = 34, provably disjoint).  Each CTA
// persists over 8 chunks (126 rows) of one column band.
// ---------------------------------------------------------------------------

#define NIMG 8
#define HIN  506
#define WIN  506
#define CIN  32
#define OHW  504
#define NB   36

#define TCOLS 32
#define XC    34              // input cols per band (32 + 2 halo)
#define PXB   80              // bytes per pixel (64B fp16 + 16 pad) -> ldmatrix
                              // phases conflict-free (i*80 mod 128 all distinct)
#define RING  34              // ring rows
#define W_OFF (RING * XC * PXB)               // 92480
#define SMEM_BYTES (W_OFF + 9 * 2048)         // 110912 -> 2 CTAs/SM

#define THREADS 320           // warps 0-7 compute, 8-9 produce
#define NCH   8               // chunks per segment (7x16 + 14 = 126 rows)
#define SEGR  126             // output rows per segment

__device__ float d_active[NIMG * NB * NB];

// ------------------------------ helpers ------------------------------------
__device__ __forceinline__ uint32_t s2u(const void* p){
    uint32_t a;
    asm("{ .reg .u64 t; cvta.to.shared.u64 t, %1; cvt.u32.u64 %0, t; }"
        : "=r"(a) : "l"(p));
    return a;
}
__device__ __forceinline__ uint32_t packh2(float lo, float hi){
    __half2 h = __floats2half2_rn(lo, hi);
    return *(uint32_t*)&h;
}
__device__ __forceinline__ void ldmA(uint32_t& a0, uint32_t& a1,
                                     uint32_t& a2, uint32_t& a3, uint32_t saddr){
    asm volatile("ldmatrix.sync.aligned.m8n8.x4.shared.b16 {%0,%1,%2,%3}, [%4];"
                 : "=r"(a0), "=r"(a1), "=r"(a2), "=r"(a3) : "r"(saddr));
}
__device__ __forceinline__ void mma16(float* c,
                                      uint32_t a0, uint32_t a1, uint32_t a2, uint32_t a3,
                                      uint32_t b0, uint32_t b1){
    asm volatile(
        "mma.sync.aligned.m16n8k16.row.col.f32.f16.f16.f32 "
        "{%0,%1,%2,%3}, {%4,%5,%6,%7}, {%8,%9}, {%0,%1,%2,%3};"
        : "+f"(c[0]), "+f"(c[1]), "+f"(c[2]), "+f"(c[3])
        : "r"(a0), "r"(a1), "r"(a2), "r"(a3), "r"(b0), "r"(b1));
}
// stage one pixel (32 fp32 -> 16B x4 fp16) into ring slot; zero-fill OOB
__device__ __forceinline__ void stage_px(char* xs, int slot, int tc,
                                         const float* __restrict__ x,
                                         int n, int grow, int gcol){
    uint4* dst = (uint4*)(xs + (slot * XC + tc) * PXB);
    if (grow < HIN && gcol < WIN){
        const float4* src = (const float4*)(x + (((size_t)n*HIN + grow)*WIN + gcol)*CIN);
#pragma unroll
        for (int q = 0; q < 4; q++){
            float4 v0 = src[q*2], v1 = src[q*2+1];
            dst[q] = make_uint4(packh2(v0.x, v0.y), packh2(v0.z, v0.w),
                                packh2(v1.x, v1.y), packh2(v1.z, v1.w));
        }
    } else {
#pragma unroll
        for (int q = 0; q < 4; q++) dst[q] = make_uint4(0u,0u,0u,0u);
    }
}

// ------------------------- active-flag kernel ------------------------------
__global__ void __launch_bounds__(256)
active_kernel(const float* __restrict__ mask){
    int w    = blockIdx.x * 8 + (threadIdx.x >> 5);
    int lane = threadIdx.x & 31;
    int n    = w / (NB*NB);
    int rem  = w - n * (NB*NB);
    int bi   = rem / NB;
    int bj   = rem - bi * NB;
    float m = -1e30f;
#pragma unroll
    for (int i = 0; i < 8; i++){
        int e = lane + 32*i, rr = e >> 4, cc = e & 15;
        m = fmaxf(m, mask[((size_t)n*HIN + bi*14 + rr)*WIN + (bj*14 + cc)]);
    }
#pragma unroll
    for (int off = 16; off; off >>= 1)
        m = fmaxf(m, __shfl_xor_sync(0xffffffffu, m, off));
    if (lane == 0) d_active[w] = (m > 0.5f) ? 1.0f : 0.0f;
}

// ----------------------------- conv kernel ---------------------------------
extern __shared__ char smem[];

__global__ void __launch_bounds__(THREADS, 2)
conv_mma(const float* __restrict__ x, const float* __restrict__ kern,
         const float* __restrict__ bias, float* __restrict__ out){
    const int tid  = threadIdx.x;
    const int wid  = tid >> 5;        // 0..9
    const int lane = tid & 31;
    const int g    = lane >> 2;
    const int t4   = lane & 3;

    const int c0   = blockIdx.x * TCOLS;       // 0..480
    const int seg0 = blockIdx.y * SEGR;        // 0,126,252,378
    const int n    = blockIdx.z;

    char* xs = smem;
    char* ws = smem + W_OFF;
    const uint32_t xs_u = s2u(xs);

    // ---- stage weights (warps 0-8, one tap each), fragment order, fp16 ----
    for (int t = wid; t < 9; t += 10){
        const float* kt = kern + t * 1024;     // [ci][co]
        char* base = ws + t * 2048 + lane * 64;
#pragma unroll
        for (int q = 0; q < 4; q++){
            int ks = q >> 1, nfp = q & 1;
            int kb = ks*16 + 2*t4;
            uint4 u;
            {
                int co = (2*nfp)*8 + g;
                u.x = packh2(kt[kb*32 + co],     kt[(kb+1)*32 + co]);
                u.y = packh2(kt[(kb+8)*32 + co], kt[(kb+9)*32 + co]);
            }
            {
                int co = (2*nfp+1)*8 + g;
                u.z = packh2(kt[kb*32 + co],     kt[(kb+1)*32 + co]);
                u.w = packh2(kt[(kb+8)*32 + co], kt[(kb+9)*32 + co]);
            }
            *(uint4*)(base + ((q ^ ((lane>>1)&3)) * 16)) = u;
        }
    }

    // ---- prologue: stage input rows seg0..seg0+17 into slots 0..17 ----
    for (int e = tid; e < 18*XC; e += THREADS){
        int tr = e / XC, tc = e - tr*XC;
        stage_px(xs, tr, tc, x, n, seg0 + tr, c0 + tc);
    }
    __syncthreads();

    const int rowb = wid * 2;                  // compute warps: 0..14
    const uint32_t laneoff = (uint32_t)((lane & 15) * PXB + (lane >> 4) * 16);
    float2 bv[4];
#pragma unroll
    for (int nf = 0; nf < 4; nf++)
        bv[nf] = *(const float2*)(bias + nf*8 + 2*t4);
    const float* act = d_active + n * (NB*NB);

    int sb = 0;                                // ring slot of chunk base row
    for (int c = 0; c < NCH; c++){
        if (wid >= 8){
            // ---- producers: stage next chunk's 16 new rows (local c*16+18..+33)
            if (c < NCH-1){
                int ptid = tid - 256;          // 0..63
                int ps = sb + 18; if (ps >= RING) ps -= RING;
#pragma unroll
                for (int j = 0; j < 9; j++){
                    int e = ptid + 64*j;
                    if (e < 16*XC){
                        int ri = e / XC, tc = e - ri*XC;
                        int s = ps + ri; if (s >= RING) s -= RING;
                        stage_px(xs, s, tc, x, n, seg0 + c*16 + 18 + ri, c0 + tc);
                    }
                }
            }
        } else {
            // ---- compute warps: chunk c, out rows (local) c*16+rowb, +1 ----
            float acc[4][4][4];
#pragma unroll
            for (int f = 0; f < 4; f++)
#pragma unroll
                for (int nf = 0; nf < 4; nf++)
#pragma unroll
                    for (int i = 0; i < 4; i++) acc[f][nf][i] = 0.0f;

            for (int dr = 0; dr < 3; dr++){
                for (int dc = 0; dc < 3; dc++){
                    uint32_t fb[16];
                    const char* wt = ws + (dr*3 + dc) * 2048 + lane * 64;
#pragma unroll
                    for (int q = 0; q < 4; q++)
                        *(uint4*)&fb[q*4] = *(const uint4*)(wt + ((q ^ ((lane>>1)&3)) * 16));

#pragma unroll
                    for (int f = 0; f < 4; f++){
                        int s = sb + rowb + (f >> 1) + dr;
                        if (s >= RING) s -= RING;
                        const int coff = (f & 1) * 16 + dc;
                        const uint32_t abase = xs_u + (uint32_t)((s*XC + coff) * PXB) + laneoff;
#pragma unroll
                        for (int ks = 0; ks < 2; ks++){
                            uint32_t a0, a1, a2, a3;
                            ldmA(a0, a1, a2, a3, abase + ks*32);
#pragma unroll
                            for (int nf = 0; nf < 4; nf++){
                                int qb = (ks*2 + (nf>>1))*4 + (nf&1)*2;
                                mma16(acc[f][nf], a0, a1, a2, a3, fb[qb], fb[qb+1]);
                            }
                        }
                    }
                }
            }

            // ---- epilogue ----
#pragma unroll
            for (int f = 0; f < 4; f++){
                const int lrow = c*16 + rowb + (f >> 1);
                if (lrow < SEGR){
                    const int row = seg0 + lrow;
                    const int rb  = (row / 14) * NB;
                    float* obase = out + (((size_t)n*OHW + row)*OHW) * CIN;
#pragma unroll
                    for (int h = 0; h < 2; h++){
                        int col = c0 + (f & 1)*16 + g + h*8;
                        if (col < OHW){
                            float fa = act[rb + col/14];
                            float* op = obase + (size_t)col * CIN + 2*t4;
#pragma unroll
                            for (int nf = 0; nf < 4; nf++){
                                float2 v;
                                v.x = (acc[f][nf][h*2 + 0] + bv[nf].x) * fa;
                                v.y = (acc[f][nf][h*2 + 1] + bv[nf].y) * fa;
                                *(float2*)(op + nf*8) = v;
                            }
                        }
                    }
                }
            }
        }
        sb += 16; if (sb >= RING) sb -= RING;
        __syncthreads();
    }
}

// ------------------------------- launch ------------------------------------
extern "C" void kernel_launch(void* const* d_in, const int* in_sizes, int n_in,
                              void* d_out, int out_size){
    const float* x    = (const float*)d_in[0];
    const float* mask = (const float*)d_in[1];
    const float* kern = (const float*)d_in[2];
    const float* bias = (const float*)d_in[3];
    float* out = (float*)d_out;

    active_kernel<<<1296, 256>>>(mask);

    cudaFuncSetAttribute(conv_mma, cudaFuncAttributeMaxDynamicSharedMemorySize,
                         SMEM_BYTES);
    dim3 grid(16, 4, NIMG);    // col bands x row segments x images = 512 CTAs
    conv_mma<<<grid, THREADS, SMEM_BYTES>>>(x, kern, bias, out);
}

// round 14
// speedup vs baseline: 1.0739x; 1.0739x over previous
#include <cuda_runtime.h>
#include <cuda_fp16.h>
#include <cstdint>

// ---------------------------------------------------------------------------
// SparseConv2D == dense VALID 3x3 conv (R3 derivation) * per-14x14-block
// active flag.  mma.sync m16n8k16 FP16 implicit GEMM (f32 accumulate).
// R13: R9's PROVEN stride-80 layout + row-split (32 live accumulators) +
// launch_bounds(256,3) -> 3 CTAs/SM, 24 warps (was 16).  The R12 compact
// swizzle was buggy (overlapping 64B payloads) and is reverted.
// ---------------------------------------------------------------------------

#define NIMG 8
#define HIN  506
#define WIN  506
#define CIN  32
#define OHW  504
#define NB   36

#define TROWS 16              // output rows per CTA (8 warps x 2 rows)
#define TCOLS 32
#define XR    18              // input rows in tile
#define XC    34              // input cols in tile
#define PXB   80              // bytes per pixel (64B fp16 + 16 pad);
                              // i*80 mod 128 all-distinct -> conflict-free
#define XS_BYTES (XR * XC * PXB)              // 48960
#define W_OFF    XS_BYTES
#define SMEM_BYTES (W_OFF + 9 * 2048)         // 67392 -> 3 CTAs/SM (202 KB)

#define THREADS 256
#define NCHUNK  32

__device__ float d_active[NIMG * NB * NB];

// ------------------------------ helpers ------------------------------------
__device__ __forceinline__ uint32_t s2u(const void* p){
    uint32_t a;
    asm("{ .reg .u64 t; cvta.to.shared.u64 t, %1; cvt.u32.u64 %0, t; }"
        : "=r"(a) : "l"(p));
    return a;
}
__device__ __forceinline__ uint32_t packh2(float lo, float hi){
    __half2 h = __floats2half2_rn(lo, hi);
    return *(uint32_t*)&h;
}
__device__ __forceinline__ void ldmA(uint32_t& a0, uint32_t& a1,
                                     uint32_t& a2, uint32_t& a3, uint32_t saddr){
    asm volatile("ldmatrix.sync.aligned.m8n8.x4.shared.b16 {%0,%1,%2,%3}, [%4];"
                 : "=r"(a0), "=r"(a1), "=r"(a2), "=r"(a3) : "r"(saddr));
}
__device__ __forceinline__ void mma16(float* c,
                                      uint32_t a0, uint32_t a1, uint32_t a2, uint32_t a3,
                                      uint32_t b0, uint32_t b1){
    asm volatile(
        "mma.sync.aligned.m16n8k16.row.col.f32.f16.f16.f32 "
        "{%0,%1,%2,%3}, {%4,%5,%6,%7}, {%8,%9}, {%0,%1,%2,%3};"
        : "+f"(c[0]), "+f"(c[1]), "+f"(c[2]), "+f"(c[3])
        : "r"(a0), "r"(a1), "r"(a2), "r"(a3), "r"(b0), "r"(b1));
}

// ------------------------- active-flag kernel ------------------------------
__global__ void __launch_bounds__(256)
active_kernel(const float* __restrict__ mask){
    int w    = blockIdx.x * 8 + (threadIdx.x >> 5);
    int lane = threadIdx.x & 31;
    int n    = w / (NB*NB);
    int rem  = w - n * (NB*NB);
    int bi   = rem / NB;
    int bj   = rem - bi * NB;
    float m = -1e30f;
#pragma unroll
    for (int i = 0; i < 8; i++){
        int e = lane + 32*i, rr = e >> 4, cc = e & 15;
        m = fmaxf(m, mask[((size_t)n*HIN + bi*14 + rr)*WIN + (bj*14 + cc)]);
    }
#pragma unroll
    for (int off = 16; off; off >>= 1)
        m = fmaxf(m, __shfl_xor_sync(0xffffffffu, m, off));
    if (lane == 0) d_active[w] = (m > 0.5f) ? 1.0f : 0.0f;
}

// ----------------------------- conv kernel ---------------------------------
extern __shared__ char smem[];

__global__ void __launch_bounds__(THREADS, 3)
conv_mma(const float* __restrict__ x, const float* __restrict__ kern,
         const float* __restrict__ bias, float* __restrict__ out){
    const int tid  = threadIdx.x;
    const int wid  = tid >> 5;        // 0..7
    const int lane = tid & 31;
    const int g    = lane >> 2;
    const int t4   = lane & 3;

    const int c0 = blockIdx.x * TCOLS;         // 0..480
    const int R0 = blockIdx.y * TROWS;         // 0..496
    const int n  = blockIdx.z;

    char* xs = smem;
    char* ws = smem + W_OFF;
    const uint32_t xs_u = s2u(xs);

    // ---- stage weights, fragment order (64B/lane/tap), fp16 ----
    for (int t = wid; t < 9; t += 8){
        const float* kt = kern + t * 1024;     // [ci][co]
        char* base = ws + t * 2048 + lane * 64;
#pragma unroll
        for (int q = 0; q < 4; q++){
            int ks = q >> 1, nfp = q & 1;
            int kb = ks*16 + 2*t4;
            uint4 u;
            {
                int co = (2*nfp)*8 + g;
                u.x = packh2(kt[kb*32 + co],     kt[(kb+1)*32 + co]);
                u.y = packh2(kt[(kb+8)*32 + co], kt[(kb+9)*32 + co]);
            }
            {
                int co = (2*nfp+1)*8 + g;
                u.z = packh2(kt[kb*32 + co],     kt[(kb+1)*32 + co]);
                u.w = packh2(kt[(kb+8)*32 + co], kt[(kb+9)*32 + co]);
            }
            *(uint4*)(base + ((q ^ ((lane>>1)&3)) * 16)) = u;
        }
    }

    // ---- stage x tile: 18x34 pixels, fp16 natural ci order, stride 80B ----
    for (int e = tid; e < XR*XC; e += THREADS){
        int tr = e / XC, tc = e - tr*XC;
        int hh = R0 + tr, wc = c0 + tc;
        uint4* dst = (uint4*)(xs + e * PXB);
        if (hh < HIN && wc < WIN){
            const float4* src = (const float4*)(x + (((size_t)n*HIN + hh)*WIN + wc)*CIN);
#pragma unroll
            for (int q = 0; q < 4; q++){
                float4 v0 = src[q*2], v1 = src[q*2+1];
                dst[q] = make_uint4(packh2(v0.x, v0.y), packh2(v0.z, v0.w),
                                    packh2(v1.x, v1.y), packh2(v1.z, v1.w));
            }
        } else {
#pragma unroll
            for (int q = 0; q < 4; q++) dst[q] = make_uint4(0u,0u,0u,0u);
        }
    }
    __syncthreads();

    const int rowb = wid * 2;
    const uint32_t laneoff = (uint32_t)((lane & 15) * PXB + (lane >> 4) * 16);
    const float* act = d_active + n * (NB*NB);
    float2 bv[4];
#pragma unroll
    for (int nf = 0; nf < 4; nf++)
        bv[nf] = *(const float2*)(bias + nf*8 + 2*t4);

    // ---- two halves: one output row each (32 live accumulators) ----
#pragma unroll 1
    for (int h = 0; h < 2; h++){
        float acc[2][4][4];
#pragma unroll
        for (int fc = 0; fc < 2; fc++)
#pragma unroll
            for (int nf = 0; nf < 4; nf++)
#pragma unroll
                for (int i = 0; i < 4; i++) acc[fc][nf][i] = 0.0f;

        for (int dr = 0; dr < 3; dr++){
#pragma unroll
            for (int dc = 0; dc < 3; dc++){
                uint32_t fb[16];
                const char* wt = ws + (dr*3 + dc) * 2048 + lane * 64;
#pragma unroll
                for (int q = 0; q < 4; q++)
                    *(uint4*)&fb[q*4] = *(const uint4*)(wt + ((q ^ ((lane>>1)&3)) * 16));

                const int trow = rowb + h + dr;
#pragma unroll
                for (int fc = 0; fc < 2; fc++){
                    const int coff = fc * 16 + dc;
                    const uint32_t abase = xs_u
                        + (uint32_t)((trow*XC + coff) * PXB) + laneoff;
#pragma unroll
                    for (int ks = 0; ks < 2; ks++){
                        uint32_t a0, a1, a2, a3;
                        ldmA(a0, a1, a2, a3, abase + ks*32);
#pragma unroll
                        for (int nf = 0; nf < 4; nf++){
                            int qb = (ks*2 + (nf>>1))*4 + (nf&1)*2;
                            mma16(acc[fc][nf], a0, a1, a2, a3, fb[qb], fb[qb+1]);
                        }
                    }
                }
            }
        }

        // ---- epilogue for row rowb+h ----
        const int row = R0 + rowb + h;
        if (row < OHW){
            const int rb = (row / 14) * NB;
            float* obase = out + (((size_t)n*OHW + row)*OHW) * CIN;
#pragma unroll
            for (int fc = 0; fc < 2; fc++){
#pragma unroll
                for (int hh = 0; hh < 2; hh++){
                    int col = c0 + fc*16 + g + hh*8;
                    if (col < OHW){
                        float fa = act[rb + col/14];
                        float* op = obase + (size_t)col * CIN + 2*t4;
#pragma unroll
                        for (int nf = 0; nf < 4; nf++){
                            float2 v;
                            v.x = (acc[fc][nf][hh*2 + 0] + bv[nf].x) * fa;
                            v.y = (acc[fc][nf][hh*2 + 1] + bv[nf].y) * fa;
                            *(float2*)(op + nf*8) = v;
                        }
                    }
                }
            }
        }
    }
}

// ------------------------------- launch ------------------------------------
extern "C" void kernel_launch(void* const* d_in, const int* in_sizes, int n_in,
                              void* d_out, int out_size){
    const float* x    = (const float*)d_in[0];
    const float* mask = (const float*)d_in[1];
    const float* kern = (const float*)d_in[2];
    const float* bias = (const float*)d_in[3];
    float* out = (float*)d_out;

    active_kernel<<<1296, 256>>>(mask);

    cudaFuncSetAttribute(conv_mma, cudaFuncAttributeMaxDynamicSharedMemorySize,
                         SMEM_BYTES);
    dim3 grid(16, NCHUNK, NIMG);   // col bands x row chunks x images
    conv_mma<<<grid, THREADS, SMEM_BYTES>>>(x, kern, bias, out);
}